// round 1
// baseline (speedup 1.0000x reference)
#include <cuda_runtime.h>
#include <math.h>

#define B_ 1024
#define N_ 64
#define E_ 1024
#define D_ 512
#define M_ (B_*N_)   // 65536 rows

// -------- scratch (device globals; no allocation allowed) --------
__device__ float g_nk [B_*D_];
__device__ float g_k  [B_*E_];
__device__ float g_v  [B_*E_];
__device__ float g_w  [B_*E_];
__device__ float g_gw [B_*E_];
__device__ float g_vo [B_*E_];
__device__ float g_qWT[E_*E_];
__device__ float g_Sg [B_];
__device__ float g_Sb [B_];
__device__ float g_attn[M_];

// -------- LayerNorm of context (one block per batch row) --------
__global__ void ln_ctx_kernel(const float* __restrict__ ctx,
                              const float* __restrict__ gam,
                              const float* __restrict__ bet) {
    int b = blockIdx.x, tid = threadIdx.x;
    const float* x = ctx + (size_t)b * D_;
    float v0 = x[tid], v1 = x[tid + 256];
    __shared__ float r1[256], r2[256];
    r1[tid] = v0 + v1;
    r2[tid] = v0 * v0 + v1 * v1;
    __syncthreads();
    for (int o = 128; o > 0; o >>= 1) {
        if (tid < o) { r1[tid] += r1[tid + o]; r2[tid] += r2[tid + o]; }
        __syncthreads();
    }
    float mu = r1[0] * (1.0f / D_);
    float var = r2[0] * (1.0f / D_) - mu * mu;
    float rstd = rsqrtf(var + 1e-5f);
    g_nk[(size_t)b * D_ + tid]       = (v0 - mu) * rstd * gam[tid]       + bet[tid];
    g_nk[(size_t)b * D_ + tid + 256] = (v1 - mu) * rstd * gam[tid + 256] + bet[tid + 256];
}

// -------- 32x32 transpose (qW -> qWT) --------
__global__ void transpose_kernel(const float* __restrict__ in, float* __restrict__ out) {
    __shared__ float t[32][33];
    int tx = threadIdx.x, ty = threadIdx.y;
    int bx = blockIdx.x * 32, by = blockIdx.y * 32;
    #pragma unroll
    for (int i = 0; i < 32; i += 8)
        t[ty + i][tx] = in[(size_t)(by + ty + i) * E_ + bx + tx];
    __syncthreads();
    #pragma unroll
    for (int i = 0; i < 32; i += 8)
        out[(size_t)(bx + ty + i) * E_ + by + tx] = t[tx][ty + i];
}

// -------- generic NT SGEMM: C[M x 1024] = A(MxK) @ B(1024xK)^T (+bias) --------
// 64x64 tile, 256 threads, 4x4 per thread, BK=16. ldc = 1024 (all uses).
// If C2 != null: C2[row,col] = colmul[col] * (acc)   (bias must be null then)
__global__ void __launch_bounds__(256) gemm64_nt(
    const float* __restrict__ A, const float* __restrict__ Bm,
    const float* __restrict__ bias, const float* __restrict__ colmul,
    float* __restrict__ C, float* __restrict__ C2, int K) {
    __shared__ float As[16][65];
    __shared__ float Bs[16][65];
    int bm = blockIdx.y * 64, bn = blockIdx.x * 64;
    int tid = threadIdx.x;
    int ty = tid >> 4, tx = tid & 15;
    int lr = tid >> 2, lk = (tid & 3) * 4;
    float acc[4][4] = {};
    const float* Ap = A  + (size_t)(bm + lr) * K + lk;
    const float* Bp = Bm + (size_t)(bn + lr) * K + lk;
    for (int k0 = 0; k0 < K; k0 += 16) {
        float4 av = *(const float4*)(Ap + k0);
        float4 bv = *(const float4*)(Bp + k0);
        __syncthreads();
        As[lk + 0][lr] = av.x; As[lk + 1][lr] = av.y;
        As[lk + 2][lr] = av.z; As[lk + 3][lr] = av.w;
        Bs[lk + 0][lr] = bv.x; Bs[lk + 1][lr] = bv.y;
        Bs[lk + 2][lr] = bv.z; Bs[lk + 3][lr] = bv.w;
        __syncthreads();
        #pragma unroll
        for (int kk = 0; kk < 16; kk++) {
            float a[4], b[4];
            #pragma unroll
            for (int i = 0; i < 4; i++) a[i] = As[kk][ty + 16 * i];
            #pragma unroll
            for (int j = 0; j < 4; j++) b[j] = Bs[kk][tx + 16 * j];
            #pragma unroll
            for (int i = 0; i < 4; i++)
                #pragma unroll
                for (int j = 0; j < 4; j++)
                    acc[i][j] += a[i] * b[j];
        }
    }
    #pragma unroll
    for (int i = 0; i < 4; i++) {
        int row = bm + ty + 16 * i;
        #pragma unroll
        for (int j = 0; j < 4; j++) {
            int col = bn + tx + 16 * j;
            float val = acc[i][j] + (bias ? bias[col] : 0.0f);
            C[(size_t)row * 1024 + col] = val;
            if (C2) C2[(size_t)row * 1024 + col] = colmul[col] * val;
        }
    }
}

// -------- per-batch scalars: Sg[b]=sum gw;  Sb[b]=beta.w + qb.k  (warp per b) --------
__global__ void scalars_kernel(const float* __restrict__ qb,
                               const float* __restrict__ lnq_b) {
    int warp = threadIdx.x >> 5, lane = threadIdx.x & 31;
    int b = blockIdx.x * 8 + warp;
    const float* gw = g_gw + (size_t)b * E_;
    const float* w  = g_w  + (size_t)b * E_;
    const float* k  = g_k  + (size_t)b * E_;
    float sg = 0.f, sb = 0.f, cb = 0.f;
    for (int i = lane; i < E_; i += 32) {
        sg += gw[i];
        sb += lnq_b[i] * w[i];
        cb += qb[i] * k[i];
    }
    #pragma unroll
    for (int o = 16; o > 0; o >>= 1) {
        sg += __shfl_xor_sync(0xffffffffu, sg, o);
        sb += __shfl_xor_sync(0xffffffffu, sb, o);
        cb += __shfl_xor_sync(0xffffffffu, cb, o);
    }
    if (lane == 0) { g_Sg[b] = sg; g_Sb[b] = sb + cb; }
}

// -------- attn[m] = tanh(scale*(rstd*(re.gw - mu*Sg) + Sb))  (warp per row) --------
__global__ void attn_kernel(const float* __restrict__ re) {
    int warp = threadIdx.x >> 5, lane = threadIdx.x & 31;
    int m = blockIdx.x * 8 + warp;
    int b = m >> 6;
    const float* x  = re   + (size_t)m * E_;
    const float* wv = g_gw + (size_t)b * E_;
    float s1 = 0.f, s2 = 0.f, sd = 0.f;
    for (int i = lane; i < E_; i += 32) {
        float t = x[i];
        s1 += t;
        s2 += t * t;
        sd += t * wv[i];
    }
    #pragma unroll
    for (int o = 16; o > 0; o >>= 1) {
        s1 += __shfl_xor_sync(0xffffffffu, s1, o);
        s2 += __shfl_xor_sync(0xffffffffu, s2, o);
        sd += __shfl_xor_sync(0xffffffffu, sd, o);
    }
    if (lane == 0) {
        float mu = s1 * (1.0f / E_);
        float var = s2 * (1.0f / E_) - mu * mu;
        float rstd = rsqrtf(var + 1e-5f);
        float score = 0.03125f * (rstd * (sd - mu * g_Sg[b]) + g_Sb[b]);
        g_attn[m] = tanhf(score);
    }
}

// -------- main GEMM: C = re @ oW^T + attn*vo + ob   (128x128x8, 8x8/thread) --------
__global__ void __launch_bounds__(256) main_gemm(
    const float* __restrict__ A, const float* __restrict__ Bm,
    const float* __restrict__ ob, float* __restrict__ C) {
    const int K = 1024;
    __shared__ float As[8][132];
    __shared__ float Bs[8][132];
    int bm = blockIdx.y * 128, bn = blockIdx.x * 128;
    int tid = threadIdx.x;
    int ty = tid >> 4, tx = tid & 15;
    int lr = tid >> 1, lk = (tid & 1) * 4;
    float acc[8][8] = {};
    const float* Ap = A  + (size_t)(bm + lr) * K + lk;
    const float* Bp = Bm + (size_t)(bn + lr) * K + lk;
    for (int k0 = 0; k0 < K; k0 += 8) {
        float4 av = *(const float4*)(Ap + k0);
        float4 bv = *(const float4*)(Bp + k0);
        __syncthreads();
        As[lk + 0][lr] = av.x; As[lk + 1][lr] = av.y;
        As[lk + 2][lr] = av.z; As[lk + 3][lr] = av.w;
        Bs[lk + 0][lr] = bv.x; Bs[lk + 1][lr] = bv.y;
        Bs[lk + 2][lr] = bv.z; Bs[lk + 3][lr] = bv.w;
        __syncthreads();
        #pragma unroll
        for (int kk = 0; kk < 8; kk++) {
            float a[8], b[8];
            #pragma unroll
            for (int i = 0; i < 8; i++) a[i] = As[kk][ty + 16 * i];
            #pragma unroll
            for (int j = 0; j < 8; j++) b[j] = Bs[kk][tx + 16 * j];
            #pragma unroll
            for (int i = 0; i < 8; i++)
                #pragma unroll
                for (int j = 0; j < 8; j++)
                    acc[i][j] += a[i] * b[j];
        }
    }
    #pragma unroll
    for (int i = 0; i < 8; i++) {
        int row = bm + ty + 16 * i;
        float am = g_attn[row];
        const float* vo = g_vo + (size_t)(row >> 6) * E_;
        #pragma unroll
        for (int j = 0; j < 8; j++) {
            int col = bn + tx + 16 * j;
            C[(size_t)row * 1024 + col] = acc[i][j] + am * vo[col] + ob[col];
        }
    }
}

extern "C" void kernel_launch(void* const* d_in, const int* in_sizes, int n_in,
                              void* d_out, int out_size) {
    const float* re    = (const float*)d_in[0];
    const float* ctx   = (const float*)d_in[1];
    const float* qW    = (const float*)d_in[2];
    const float* qb    = (const float*)d_in[3];
    const float* kW    = (const float*)d_in[4];
    const float* kb    = (const float*)d_in[5];
    const float* vW    = (const float*)d_in[6];
    const float* vb    = (const float*)d_in[7];
    const float* oW    = (const float*)d_in[8];
    const float* ob    = (const float*)d_in[9];
    const float* lnq_g = (const float*)d_in[10];
    const float* lnq_b = (const float*)d_in[11];
    const float* lnk_g = (const float*)d_in[12];
    const float* lnk_b = (const float*)d_in[13];
    float* out = (float*)d_out;

    void *p_nk, *p_k, *p_v, *p_w, *p_gw, *p_vo, *p_qWT;
    cudaGetSymbolAddress(&p_nk,  g_nk);
    cudaGetSymbolAddress(&p_k,   g_k);
    cudaGetSymbolAddress(&p_v,   g_v);
    cudaGetSymbolAddress(&p_w,   g_w);
    cudaGetSymbolAddress(&p_gw,  g_gw);
    cudaGetSymbolAddress(&p_vo,  g_vo);
    cudaGetSymbolAddress(&p_qWT, g_qWT);
    float* nk  = (float*)p_nk;
    float* k   = (float*)p_k;
    float* v   = (float*)p_v;
    float* w   = (float*)p_w;
    float* gw  = (float*)p_gw;
    float* vo  = (float*)p_vo;
    float* qWT = (float*)p_qWT;

    // 1. nk = LN(context)
    ln_ctx_kernel<<<B_, 256>>>(ctx, lnk_g, lnk_b);
    // 2. k = nk @ kW^T + kb ; v = nk @ vW^T + vb
    gemm64_nt<<<dim3(16, 16), 256>>>(nk, kW, kb, nullptr, k, nullptr, D_);
    gemm64_nt<<<dim3(16, 16), 256>>>(nk, vW, vb, nullptr, v, nullptr, D_);
    // 3. qWT = qW^T ; w = k @ qW ; gw = lnq_g * w
    transpose_kernel<<<dim3(32, 32), dim3(32, 8)>>>(qW, qWT);
    gemm64_nt<<<dim3(16, 16), 256>>>(k, qWT, nullptr, lnq_g, w, gw, E_);
    // 4. vo = v @ oW^T
    gemm64_nt<<<dim3(16, 16), 256>>>(v, oW, nullptr, nullptr, vo, nullptr, E_);
    // 5. per-batch scalars
    scalars_kernel<<<B_ / 8, 256>>>(qb, lnq_b);
    // 6. attn per (b,n) row
    attn_kernel<<<M_ / 8, 256>>>(re);
    // 7. out = re @ oW^T + attn*vo + ob
    main_gemm<<<dim3(8, 512), 256>>>(re, oW, ob, out);
}

// round 4
// speedup vs baseline: 1.9646x; 1.9646x over previous
#include <cuda_runtime.h>
#include <cuda_bf16.h>
#include <math.h>
#include <stdint.h>

#define B_ 1024
#define N_ 64
#define E_ 1024
#define D_ 512
#define M_ (B_*N_)   // 65536 rows

// -------- scratch (device globals; no allocation allowed) --------
__device__ float g_nk [B_*D_];
__device__ float g_k  [B_*E_];
__device__ float g_v  [B_*E_];
__device__ float g_w  [B_*E_];
__device__ float g_gw [B_*E_];
__device__ float g_vo [B_*E_];
__device__ float g_qWT[E_*E_];
__device__ float g_Sg [B_];
__device__ float g_Sb [B_];
__device__ float g_attn[M_];
// bf16 split operands for the main tensor-core GEMM
__device__ __nv_bfloat16 g_Ahi[(size_t)M_*E_];
__device__ __nv_bfloat16 g_Alo[(size_t)M_*E_];
__device__ __nv_bfloat16 g_Bhi[(size_t)E_*E_];
__device__ __nv_bfloat16 g_Blo[(size_t)E_*E_];

// ================= PTX helpers (compute_103-safe: no 'a' features) ==========
__device__ __forceinline__ uint32_t smem_u32(const void* p) {
    uint32_t a;
    asm("{ .reg .u64 t; cvta.to.shared.u64 t, %1; cvt.u32.u64 %0, t; }" : "=r"(a) : "l"(p));
    return a;
}
__device__ __forceinline__ void cp16(uint32_t dst, const void* src) {
    asm volatile("cp.async.cg.shared.global [%0], [%1], 16;" :: "r"(dst), "l"(src));
}
#define CP_COMMIT() asm volatile("cp.async.commit_group;" ::: "memory")
#define CP_WAIT2()  asm volatile("cp.async.wait_group 2;" ::: "memory")

__device__ __forceinline__ void ldm4(uint32_t& r0, uint32_t& r1, uint32_t& r2,
                                     uint32_t& r3, uint32_t a) {
    asm volatile("ldmatrix.sync.aligned.m8n8.x4.shared.b16 {%0,%1,%2,%3}, [%4];"
                 : "=r"(r0), "=r"(r1), "=r"(r2), "=r"(r3) : "r"(a));
}
__device__ __forceinline__ void mma16816(float* c, const uint32_t* a,
                                         uint32_t b0, uint32_t b1) {
    asm volatile("mma.sync.aligned.m16n8k16.row.col.f32.bf16.bf16.f32 "
                 "{%0,%1,%2,%3},{%4,%5,%6,%7},{%8,%9},{%0,%1,%2,%3};"
                 : "+f"(c[0]), "+f"(c[1]), "+f"(c[2]), "+f"(c[3])
                 : "r"(a[0]), "r"(a[1]), "r"(a[2]), "r"(a[3]), "r"(b0), "r"(b1));
}

// ================= bf16 hi/lo split =================
__global__ void split_kernel(const float* __restrict__ x,
                             __nv_bfloat16* __restrict__ hi,
                             __nv_bfloat16* __restrict__ lo) {
    size_t i = ((size_t)blockIdx.x * blockDim.x + threadIdx.x) * 4;
    float4 v = *(const float4*)(x + i);
    __nv_bfloat16 h0 = __float2bfloat16(v.x), h1 = __float2bfloat16(v.y);
    __nv_bfloat16 h2 = __float2bfloat16(v.z), h3 = __float2bfloat16(v.w);
    __nv_bfloat16 l0 = __float2bfloat16(v.x - __bfloat162float(h0));
    __nv_bfloat16 l1 = __float2bfloat16(v.y - __bfloat162float(h1));
    __nv_bfloat16 l2 = __float2bfloat16(v.z - __bfloat162float(h2));
    __nv_bfloat16 l3 = __float2bfloat16(v.w - __bfloat162float(h3));
    __nv_bfloat162 hv0 = __halves2bfloat162(h0, h1), hv1 = __halves2bfloat162(h2, h3);
    __nv_bfloat162 lv0 = __halves2bfloat162(l0, l1), lv1 = __halves2bfloat162(l2, l3);
    uint2 hp, lp;
    hp.x = *(uint32_t*)&hv0; hp.y = *(uint32_t*)&hv1;
    lp.x = *(uint32_t*)&lv0; lp.y = *(uint32_t*)&lv1;
    *(uint2*)(hi + i) = hp;
    *(uint2*)(lo + i) = lp;
}

// ================= aux kernels (unchanged from R1, all passing) =================
__global__ void ln_ctx_kernel(const float* __restrict__ ctx,
                              const float* __restrict__ gam,
                              const float* __restrict__ bet) {
    int b = blockIdx.x, tid = threadIdx.x;
    const float* x = ctx + (size_t)b * D_;
    float v0 = x[tid], v1 = x[tid + 256];
    __shared__ float r1[256], r2[256];
    r1[tid] = v0 + v1;
    r2[tid] = v0 * v0 + v1 * v1;
    __syncthreads();
    for (int o = 128; o > 0; o >>= 1) {
        if (tid < o) { r1[tid] += r1[tid + o]; r2[tid] += r2[tid + o]; }
        __syncthreads();
    }
    float mu = r1[0] * (1.0f / D_);
    float var = r2[0] * (1.0f / D_) - mu * mu;
    float rstd = rsqrtf(var + 1e-5f);
    g_nk[(size_t)b * D_ + tid]       = (v0 - mu) * rstd * gam[tid]       + bet[tid];
    g_nk[(size_t)b * D_ + tid + 256] = (v1 - mu) * rstd * gam[tid + 256] + bet[tid + 256];
}

__global__ void transpose_kernel(const float* __restrict__ in, float* __restrict__ out) {
    __shared__ float t[32][33];
    int tx = threadIdx.x, ty = threadIdx.y;
    int bx = blockIdx.x * 32, by = blockIdx.y * 32;
    #pragma unroll
    for (int i = 0; i < 32; i += 8)
        t[ty + i][tx] = in[(size_t)(by + ty + i) * E_ + bx + tx];
    __syncthreads();
    #pragma unroll
    for (int i = 0; i < 32; i += 8)
        out[(size_t)(bx + ty + i) * E_ + by + tx] = t[tx][ty + i];
}

__global__ void __launch_bounds__(256) gemm64_nt(
    const float* __restrict__ A, const float* __restrict__ Bm,
    const float* __restrict__ bias, const float* __restrict__ colmul,
    float* __restrict__ C, float* __restrict__ C2, int K) {
    __shared__ float As[16][65];
    __shared__ float Bs[16][65];
    int bm = blockIdx.y * 64, bn = blockIdx.x * 64;
    int tid = threadIdx.x;
    int ty = tid >> 4, tx = tid & 15;
    int lr = tid >> 2, lk = (tid & 3) * 4;
    float acc[4][4] = {};
    const float* Ap = A  + (size_t)(bm + lr) * K + lk;
    const float* Bp = Bm + (size_t)(bn + lr) * K + lk;
    for (int k0 = 0; k0 < K; k0 += 16) {
        float4 av = *(const float4*)(Ap + k0);
        float4 bv = *(const float4*)(Bp + k0);
        __syncthreads();
        As[lk + 0][lr] = av.x; As[lk + 1][lr] = av.y;
        As[lk + 2][lr] = av.z; As[lk + 3][lr] = av.w;
        Bs[lk + 0][lr] = bv.x; Bs[lk + 1][lr] = bv.y;
        Bs[lk + 2][lr] = bv.z; Bs[lk + 3][lr] = bv.w;
        __syncthreads();
        #pragma unroll
        for (int kk = 0; kk < 16; kk++) {
            float a[4], b[4];
            #pragma unroll
            for (int i = 0; i < 4; i++) a[i] = As[kk][ty + 16 * i];
            #pragma unroll
            for (int j = 0; j < 4; j++) b[j] = Bs[kk][tx + 16 * j];
            #pragma unroll
            for (int i = 0; i < 4; i++)
                #pragma unroll
                for (int j = 0; j < 4; j++)
                    acc[i][j] += a[i] * b[j];
        }
    }
    #pragma unroll
    for (int i = 0; i < 4; i++) {
        int row = bm + ty + 16 * i;
        #pragma unroll
        for (int j = 0; j < 4; j++) {
            int col = bn + tx + 16 * j;
            float val = acc[i][j] + (bias ? bias[col] : 0.0f);
            C[(size_t)row * 1024 + col] = val;
            if (C2) C2[(size_t)row * 1024 + col] = colmul[col] * val;
        }
    }
}

__global__ void scalars_kernel(const float* __restrict__ qb,
                               const float* __restrict__ lnq_b) {
    int warp = threadIdx.x >> 5, lane = threadIdx.x & 31;
    int b = blockIdx.x * 8 + warp;
    const float* gw = g_gw + (size_t)b * E_;
    const float* w  = g_w  + (size_t)b * E_;
    const float* k  = g_k  + (size_t)b * E_;
    float sg = 0.f, sb = 0.f, cb = 0.f;
    for (int i = lane; i < E_; i += 32) {
        sg += gw[i];
        sb += lnq_b[i] * w[i];
        cb += qb[i] * k[i];
    }
    #pragma unroll
    for (int o = 16; o > 0; o >>= 1) {
        sg += __shfl_xor_sync(0xffffffffu, sg, o);
        sb += __shfl_xor_sync(0xffffffffu, sb, o);
        cb += __shfl_xor_sync(0xffffffffu, cb, o);
    }
    if (lane == 0) { g_Sg[b] = sg; g_Sb[b] = sb + cb; }
}

__global__ void attn_kernel(const float* __restrict__ re) {
    int warp = threadIdx.x >> 5, lane = threadIdx.x & 31;
    int m = blockIdx.x * 8 + warp;
    int b = m >> 6;
    const float* x  = re   + (size_t)m * E_;
    const float* wv = g_gw + (size_t)b * E_;
    float s1 = 0.f, s2 = 0.f, sd = 0.f;
    for (int i = lane; i < E_; i += 32) {
        float t = x[i];
        s1 += t;
        s2 += t * t;
        sd += t * wv[i];
    }
    #pragma unroll
    for (int o = 16; o > 0; o >>= 1) {
        s1 += __shfl_xor_sync(0xffffffffu, s1, o);
        s2 += __shfl_xor_sync(0xffffffffu, s2, o);
        sd += __shfl_xor_sync(0xffffffffu, sd, o);
    }
    if (lane == 0) {
        float mu = s1 * (1.0f / E_);
        float var = s2 * (1.0f / E_) - mu * mu;
        float rstd = rsqrtf(var + 1e-5f);
        float score = 0.03125f * (rstd * (sd - mu * g_Sg[b]) + g_Sb[b]);
        g_attn[m] = tanhf(score);
    }
}

// ================= main GEMM via mma.sync (HMMA bf16) =================
// out[M_ x 1024] = re @ oW^T + attn*vo + ob, 3-term bf16 split across K:
//   iters 0-31: Ahi x Bhi; 32-63: Alo x Bhi; 64-95: Ahi x Blo  (BK=32)
// CTA tile 128x256, 512 threads, warp tile 64x32, 4-stage cp.async pipeline.
// Smem rows padded to 80B (5x16B, odd -> conflict-free ldmatrix).
#define MG_STAGES 4
#define MG_AROWB  80
#define MG_ASZ    (128*MG_AROWB)            // 10240
#define MG_BSZ    (256*MG_AROWB)            // 20480
#define MG_STGSZ  (MG_ASZ + MG_BSZ)         // 30720
#define MG_ITERS  96

__device__ __forceinline__ void mg_issue(uint32_t sbase, int stage, int it,
                                         int bm, int bn, int tid) {
    int ph = it >> 5;
    int kk = (it & 31) << 5;
    const __nv_bfloat16* Asrc = (ph == 1) ? g_Alo : g_Ahi;
    const __nv_bfloat16* Bsrc = (ph == 2) ? g_Blo : g_Bhi;
    uint32_t ab = sbase + stage * MG_STGSZ;
    uint32_t bb = ab + MG_ASZ;
    // A: 512 chunks of 16B, 1 per thread
    int ar = tid >> 2, ac = tid & 3;
    cp16(ab + ar * MG_AROWB + ac * 16,
         Asrc + (size_t)(bm + ar) * E_ + kk + ac * 8);
    // B: 1024 chunks, 2 per thread
    #pragma unroll
    for (int j = 0; j < 2; j++) {
        int id = tid + j * 512;
        int br = id >> 2, bc = id & 3;
        cp16(bb + br * MG_AROWB + bc * 16,
             Bsrc + (size_t)(bn + br) * E_ + kk + bc * 8);
    }
}

__global__ void __launch_bounds__(512, 1) main_gemm_mma(const float* __restrict__ ob,
                                                        float* __restrict__ out) {
    extern __shared__ char smem[];
    uint32_t sbase = smem_u32(smem);
    int tid = threadIdx.x, wid = tid >> 5, lane = tid & 31;
    int bm = blockIdx.y * 128, bn = blockIdx.x * 256;
    int wm = wid & 1, wn = wid >> 1;          // warp tile: rows wm*64, cols wn*32

    float acc[4][4][4] = {};

    mg_issue(sbase, 0, 0, bm, bn, tid); CP_COMMIT();
    mg_issue(sbase, 1, 1, bm, bn, tid); CP_COMMIT();
    mg_issue(sbase, 2, 2, bm, bn, tid); CP_COMMIT();

    int l15 = lane & 15, l16 = lane >> 4;

    for (int i = 0; i < MG_ITERS; i++) {
        CP_WAIT2();
        __syncthreads();
        int s = i & 3;
        uint32_t ab = sbase + s * MG_STGSZ;
        uint32_t bb = ab + MG_ASZ;
        #pragma unroll
        for (int ks = 0; ks < 2; ks++) {
            int kc = ks * 2;
            uint32_t aaddr = ab + (wm * 64 + l15) * MG_AROWB + (kc + l16) * 16;
            uint32_t baddr = bb + (wn * 32 + l15) * MG_AROWB + (kc + l16) * 16;
            uint32_t ar[4][4], br[2][4];
            #pragma unroll
            for (int mi = 0; mi < 4; mi++)
                ldm4(ar[mi][0], ar[mi][1], ar[mi][2], ar[mi][3],
                     aaddr + mi * 16 * MG_AROWB);
            #pragma unroll
            for (int nb = 0; nb < 2; nb++)
                ldm4(br[nb][0], br[nb][1], br[nb][2], br[nb][3],
                     baddr + nb * 16 * MG_AROWB);
            #pragma unroll
            for (int mi = 0; mi < 4; mi++) {
                #pragma unroll
                for (int nb = 0; nb < 2; nb++) {
                    mma16816(acc[mi][2 * nb + 0], ar[mi], br[nb][0], br[nb][2]);
                    mma16816(acc[mi][2 * nb + 1], ar[mi], br[nb][1], br[nb][3]);
                }
            }
        }
        if (i + 3 < MG_ITERS)
            mg_issue(sbase, (i + 3) & 3, i + 3, bm, bn, tid);
        CP_COMMIT();   // always commit (possibly empty group) to keep counts uniform
    }

    // epilogue: acc[mi][ni]: rows bm+wm*64+mi*16+lane/4 (+8), cols bn+wn*32+ni*8+(lane%4)*2
    int lr = lane >> 2, lc = (lane & 3) * 2;
    #pragma unroll
    for (int mi = 0; mi < 4; mi++) {
        int row0 = bm + wm * 64 + mi * 16 + lr;
        int row1 = row0 + 8;
        float am0 = g_attn[row0], am1 = g_attn[row1];
        const float* vo0 = g_vo + (size_t)(row0 >> 6) * E_;
        const float* vo1 = g_vo + (size_t)(row1 >> 6) * E_;
        float* o0 = out + (size_t)row0 * E_;
        float* o1 = out + (size_t)row1 * E_;
        #pragma unroll
        for (int ni = 0; ni < 4; ni++) {
            int col = bn + wn * 32 + ni * 8 + lc;
            float2 r0, r1;
            r0.x = acc[mi][ni][0] + am0 * vo0[col]     + ob[col];
            r0.y = acc[mi][ni][1] + am0 * vo0[col + 1] + ob[col + 1];
            r1.x = acc[mi][ni][2] + am1 * vo1[col]     + ob[col];
            r1.y = acc[mi][ni][3] + am1 * vo1[col + 1] + ob[col + 1];
            *(float2*)(o0 + col) = r0;
            *(float2*)(o1 + col) = r1;
        }
    }
}

extern "C" void kernel_launch(void* const* d_in, const int* in_sizes, int n_in,
                              void* d_out, int out_size) {
    const float* re    = (const float*)d_in[0];
    const float* ctx   = (const float*)d_in[1];
    const float* qW    = (const float*)d_in[2];
    const float* qb    = (const float*)d_in[3];
    const float* kW    = (const float*)d_in[4];
    const float* kb    = (const float*)d_in[5];
    const float* vW    = (const float*)d_in[6];
    const float* vb    = (const float*)d_in[7];
    const float* oW    = (const float*)d_in[8];
    const float* ob    = (const float*)d_in[9];
    const float* lnq_g = (const float*)d_in[10];
    const float* lnq_b = (const float*)d_in[11];
    const float* lnk_g = (const float*)d_in[12];
    const float* lnk_b = (const float*)d_in[13];
    float* out = (float*)d_out;

    void *p_nk, *p_k, *p_v, *p_w, *p_gw, *p_vo, *p_qWT, *p_ahi, *p_alo, *p_bhi, *p_blo;
    cudaGetSymbolAddress(&p_nk,  g_nk);
    cudaGetSymbolAddress(&p_k,   g_k);
    cudaGetSymbolAddress(&p_v,   g_v);
    cudaGetSymbolAddress(&p_w,   g_w);
    cudaGetSymbolAddress(&p_gw,  g_gw);
    cudaGetSymbolAddress(&p_vo,  g_vo);
    cudaGetSymbolAddress(&p_qWT, g_qWT);
    cudaGetSymbolAddress(&p_ahi, g_Ahi);
    cudaGetSymbolAddress(&p_alo, g_Alo);
    cudaGetSymbolAddress(&p_bhi, g_Bhi);
    cudaGetSymbolAddress(&p_blo, g_Blo);
    float* nk  = (float*)p_nk;
    float* k   = (float*)p_k;
    float* v   = (float*)p_v;
    float* w   = (float*)p_w;
    float* gw  = (float*)p_gw;
    float* vo  = (float*)p_vo;
    float* qWT = (float*)p_qWT;

    // 0. bf16 hi/lo splits for the main GEMM operands
    split_kernel<<<(size_t)M_ * E_ / 4 / 256, 256>>>(re, (__nv_bfloat16*)p_ahi, (__nv_bfloat16*)p_alo);
    split_kernel<<<(size_t)E_ * E_ / 4 / 256, 256>>>(oW, (__nv_bfloat16*)p_bhi, (__nv_bfloat16*)p_blo);
    // 1. nk = LN(context)
    ln_ctx_kernel<<<B_, 256>>>(ctx, lnk_g, lnk_b);
    // 2. k = nk @ kW^T + kb ; v = nk @ vW^T + vb
    gemm64_nt<<<dim3(16, 16), 256>>>(nk, kW, kb, nullptr, k, nullptr, D_);
    gemm64_nt<<<dim3(16, 16), 256>>>(nk, vW, vb, nullptr, v, nullptr, D_);
    // 3. qWT = qW^T ; w = k @ qW ; gw = lnq_g * w
    transpose_kernel<<<dim3(32, 32), dim3(32, 8)>>>(qW, qWT);
    gemm64_nt<<<dim3(16, 16), 256>>>(k, qWT, nullptr, lnq_g, w, gw, E_);
    // 4. vo = v @ oW^T
    gemm64_nt<<<dim3(16, 16), 256>>>(v, oW, nullptr, nullptr, vo, nullptr, E_);
    // 5. per-batch scalars
    scalars_kernel<<<B_ / 8, 256>>>(qb, lnq_b);
    // 6. attn per (b,n) row
    attn_kernel<<<M_ / 8, 256>>>(re);
    // 7. out = re @ oW^T + attn*vo + ob  (mma.sync bf16 3-term)
    const int smem_bytes = MG_STAGES * MG_STGSZ;   // 122880
    cudaFuncSetAttribute(main_gemm_mma, cudaFuncAttributeMaxDynamicSharedMemorySize, smem_bytes);
    main_gemm_mma<<<dim3(4, 512), 512, smem_bytes>>>(ob, out);
}

// round 5
// speedup vs baseline: 2.8933x; 1.4727x over previous
#include <cuda_runtime.h>
#include <cuda_fp16.h>
#include <math.h>
#include <stdint.h>

#define B_ 1024
#define N_ 64
#define E_ 1024
#define D_ 512
#define M_ (B_*N_)   // 65536 rows

// -------- scratch (device globals; no allocation allowed) --------
__device__ float g_nk [B_*D_];
__device__ float g_k  [B_*E_];
__device__ float g_v  [B_*E_];
__device__ float g_w  [B_*E_];
__device__ float g_gw [B_*E_];
__device__ float g_vo [B_*E_];
__device__ float g_qWT[E_*E_];
__device__ float g_Sg [B_];
__device__ float g_Sb [B_];
__device__ float g_attn[M_];
// fp16 split operands for the main tensor-core GEMM
__device__ __half g_Ahi[(size_t)M_*E_];
__device__ __half g_Alo[(size_t)M_*E_];
__device__ __half g_Bh [(size_t)E_*E_];

// ================= PTX helpers (compute_103-safe: no 'a' features) ==========
__device__ __forceinline__ uint32_t smem_u32(const void* p) {
    uint32_t a;
    asm("{ .reg .u64 t; cvta.to.shared.u64 t, %1; cvt.u32.u64 %0, t; }" : "=r"(a) : "l"(p));
    return a;
}
__device__ __forceinline__ void cp16(uint32_t dst, const void* src) {
    asm volatile("cp.async.cg.shared.global [%0], [%1], 16;" :: "r"(dst), "l"(src));
}
#define CP_COMMIT() asm volatile("cp.async.commit_group;" ::: "memory")
#define CP_WAIT2()  asm volatile("cp.async.wait_group 2;" ::: "memory")

__device__ __forceinline__ void ldm4(uint32_t& r0, uint32_t& r1, uint32_t& r2,
                                     uint32_t& r3, uint32_t a) {
    asm volatile("ldmatrix.sync.aligned.m8n8.x4.shared.b16 {%0,%1,%2,%3}, [%4];"
                 : "=r"(r0), "=r"(r1), "=r"(r2), "=r"(r3) : "r"(a));
}
__device__ __forceinline__ void mma16816(float* c, const uint32_t* a,
                                         uint32_t b0, uint32_t b1) {
    asm volatile("mma.sync.aligned.m16n8k16.row.col.f32.f16.f16.f32 "
                 "{%0,%1,%2,%3},{%4,%5,%6,%7},{%8,%9},{%0,%1,%2,%3};"
                 : "+f"(c[0]), "+f"(c[1]), "+f"(c[2]), "+f"(c[3])
                 : "r"(a[0]), "r"(a[1]), "r"(a[2]), "r"(a[3]), "r"(b0), "r"(b1));
}

// ================= fp16 splits =================
__global__ void splitA_kernel(const float* __restrict__ x,
                              __half* __restrict__ hi,
                              __half* __restrict__ lo) {
    size_t i = ((size_t)blockIdx.x * blockDim.x + threadIdx.x) * 4;
    float4 v = *(const float4*)(x + i);
    __half h0 = __float2half(v.x), h1 = __float2half(v.y);
    __half h2 = __float2half(v.z), h3 = __float2half(v.w);
    __half l0 = __float2half(v.x - __half2float(h0));
    __half l1 = __float2half(v.y - __half2float(h1));
    __half l2 = __float2half(v.z - __half2float(h2));
    __half l3 = __float2half(v.w - __half2float(h3));
    __half2 hv0 = __halves2half2(h0, h1), hv1 = __halves2half2(h2, h3);
    __half2 lv0 = __halves2half2(l0, l1), lv1 = __halves2half2(l2, l3);
    uint2 hp, lp;
    hp.x = *(uint32_t*)&hv0; hp.y = *(uint32_t*)&hv1;
    lp.x = *(uint32_t*)&lv0; lp.y = *(uint32_t*)&lv1;
    *(uint2*)(hi + i) = hp;
    *(uint2*)(lo + i) = lp;
}

__global__ void cvtB_kernel(const float* __restrict__ x, __half* __restrict__ h) {
    size_t i = ((size_t)blockIdx.x * blockDim.x + threadIdx.x) * 4;
    float4 v = *(const float4*)(x + i);
    __half2 a = __halves2half2(__float2half(v.x), __float2half(v.y));
    __half2 b = __halves2half2(__float2half(v.z), __float2half(v.w));
    uint2 p;
    p.x = *(uint32_t*)&a; p.y = *(uint32_t*)&b;
    *(uint2*)(h + i) = p;
}

// ================= aux kernels (unchanged, all passing) =================
__global__ void ln_ctx_kernel(const float* __restrict__ ctx,
                              const float* __restrict__ gam,
                              const float* __restrict__ bet) {
    int b = blockIdx.x, tid = threadIdx.x;
    const float* x = ctx + (size_t)b * D_;
    float v0 = x[tid], v1 = x[tid + 256];
    __shared__ float r1[256], r2[256];
    r1[tid] = v0 + v1;
    r2[tid] = v0 * v0 + v1 * v1;
    __syncthreads();
    for (int o = 128; o > 0; o >>= 1) {
        if (tid < o) { r1[tid] += r1[tid + o]; r2[tid] += r2[tid + o]; }
        __syncthreads();
    }
    float mu = r1[0] * (1.0f / D_);
    float var = r2[0] * (1.0f / D_) - mu * mu;
    float rstd = rsqrtf(var + 1e-5f);
    g_nk[(size_t)b * D_ + tid]       = (v0 - mu) * rstd * gam[tid]       + bet[tid];
    g_nk[(size_t)b * D_ + tid + 256] = (v1 - mu) * rstd * gam[tid + 256] + bet[tid + 256];
}

__global__ void transpose_kernel(const float* __restrict__ in, float* __restrict__ out) {
    __shared__ float t[32][33];
    int tx = threadIdx.x, ty = threadIdx.y;
    int bx = blockIdx.x * 32, by = blockIdx.y * 32;
    #pragma unroll
    for (int i = 0; i < 32; i += 8)
        t[ty + i][tx] = in[(size_t)(by + ty + i) * E_ + bx + tx];
    __syncthreads();
    #pragma unroll
    for (int i = 0; i < 32; i += 8)
        out[(size_t)(bx + ty + i) * E_ + by + tx] = t[tx][ty + i];
}

__global__ void __launch_bounds__(256) gemm64_nt(
    const float* __restrict__ A, const float* __restrict__ Bm,
    const float* __restrict__ bias, const float* __restrict__ colmul,
    float* __restrict__ C, float* __restrict__ C2, int K) {
    __shared__ float As[16][65];
    __shared__ float Bs[16][65];
    int bm = blockIdx.y * 64, bn = blockIdx.x * 64;
    int tid = threadIdx.x;
    int ty = tid >> 4, tx = tid & 15;
    int lr = tid >> 2, lk = (tid & 3) * 4;
    float acc[4][4] = {};
    const float* Ap = A  + (size_t)(bm + lr) * K + lk;
    const float* Bp = Bm + (size_t)(bn + lr) * K + lk;
    for (int k0 = 0; k0 < K; k0 += 16) {
        float4 av = *(const float4*)(Ap + k0);
        float4 bv = *(const float4*)(Bp + k0);
        __syncthreads();
        As[lk + 0][lr] = av.x; As[lk + 1][lr] = av.y;
        As[lk + 2][lr] = av.z; As[lk + 3][lr] = av.w;
        Bs[lk + 0][lr] = bv.x; Bs[lk + 1][lr] = bv.y;
        Bs[lk + 2][lr] = bv.z; Bs[lk + 3][lr] = bv.w;
        __syncthreads();
        #pragma unroll
        for (int kk = 0; kk < 16; kk++) {
            float a[4], b[4];
            #pragma unroll
            for (int i = 0; i < 4; i++) a[i] = As[kk][ty + 16 * i];
            #pragma unroll
            for (int j = 0; j < 4; j++) b[j] = Bs[kk][tx + 16 * j];
            #pragma unroll
            for (int i = 0; i < 4; i++)
                #pragma unroll
                for (int j = 0; j < 4; j++)
                    acc[i][j] += a[i] * b[j];
        }
    }
    #pragma unroll
    for (int i = 0; i < 4; i++) {
        int row = bm + ty + 16 * i;
        #pragma unroll
        for (int j = 0; j < 4; j++) {
            int col = bn + tx + 16 * j;
            float val = acc[i][j] + (bias ? bias[col] : 0.0f);
            C[(size_t)row * 1024 + col] = val;
            if (C2) C2[(size_t)row * 1024 + col] = colmul[col] * val;
        }
    }
}

__global__ void scalars_kernel(const float* __restrict__ qb,
                               const float* __restrict__ lnq_b) {
    int warp = threadIdx.x >> 5, lane = threadIdx.x & 31;
    int b = blockIdx.x * 8 + warp;
    const float* gw = g_gw + (size_t)b * E_;
    const float* w  = g_w  + (size_t)b * E_;
    const float* k  = g_k  + (size_t)b * E_;
    float sg = 0.f, sb = 0.f, cb = 0.f;
    for (int i = lane; i < E_; i += 32) {
        sg += gw[i];
        sb += lnq_b[i] * w[i];
        cb += qb[i] * k[i];
    }
    #pragma unroll
    for (int o = 16; o > 0; o >>= 1) {
        sg += __shfl_xor_sync(0xffffffffu, sg, o);
        sb += __shfl_xor_sync(0xffffffffu, sb, o);
        cb += __shfl_xor_sync(0xffffffffu, cb, o);
    }
    if (lane == 0) { g_Sg[b] = sg; g_Sb[b] = sb + cb; }
}

__global__ void attn_kernel(const float* __restrict__ re) {
    int warp = threadIdx.x >> 5, lane = threadIdx.x & 31;
    int m = blockIdx.x * 8 + warp;
    int b = m >> 6;
    const float* x  = re   + (size_t)m * E_;
    const float* wv = g_gw + (size_t)b * E_;
    float s1 = 0.f, s2 = 0.f, sd = 0.f;
    for (int i = lane; i < E_; i += 32) {
        float t = x[i];
        s1 += t;
        s2 += t * t;
        sd += t * wv[i];
    }
    #pragma unroll
    for (int o = 16; o > 0; o >>= 1) {
        s1 += __shfl_xor_sync(0xffffffffu, s1, o);
        s2 += __shfl_xor_sync(0xffffffffu, s2, o);
        sd += __shfl_xor_sync(0xffffffffu, sd, o);
    }
    if (lane == 0) {
        float mu = s1 * (1.0f / E_);
        float var = s2 * (1.0f / E_) - mu * mu;
        float rstd = rsqrtf(var + 1e-5f);
        float score = 0.03125f * (rstd * (sd - mu * g_Sg[b]) + g_Sb[b]);
        g_attn[m] = tanhf(score);
    }
}

// ================= main GEMM via mma.sync (fp16 2-term) =================
// out = re @ oW^T + attn*vo + ob;   re = Ahi + Alo (fp16 split), oW -> Bh fp16.
// Per k-chunk: acc += Ahi_chunk x B_chunk + Alo_chunk x B_chunk  (shared B tile).
// CTA tile 128x256, 512 threads, warp tile 64x32, BK=32, 4-stage cp.async.
// Smem rows padded to 80B (odd 16B stride -> conflict-free ldmatrix).
#define MG_STAGES 4
#define MG_AROWB  80
#define MG_ASZ    (128*MG_AROWB)            // 10240
#define MG_BSZ    (256*MG_AROWB)            // 20480
#define MG_STGSZ  (2*MG_ASZ + MG_BSZ)       // 40960
#define MG_ITERS  32

__device__ __forceinline__ void mg_issue(uint32_t sbase, int stage, int it,
                                         int bm, int bn, int tid) {
    int kk = it << 5;
    uint32_t ab = sbase + stage * MG_STGSZ;
    uint32_t bb = ab + 2 * MG_ASZ;
    int ar = tid >> 2, ac = tid & 3;
    size_t aoff = (size_t)(bm + ar) * E_ + kk + ac * 8;
    cp16(ab + ar * MG_AROWB + ac * 16, g_Ahi + aoff);
    cp16(ab + MG_ASZ + ar * MG_AROWB + ac * 16, g_Alo + aoff);
    #pragma unroll
    for (int j = 0; j < 2; j++) {
        int id = tid + j * 512;
        int br = id >> 2, bc = id & 3;
        cp16(bb + br * MG_AROWB + bc * 16,
             g_Bh + (size_t)(bn + br) * E_ + kk + bc * 8);
    }
}

__global__ void __launch_bounds__(512, 1) main_gemm_mma(const float* __restrict__ ob,
                                                        float* __restrict__ out) {
    extern __shared__ char smem[];
    uint32_t sbase = smem_u32(smem);
    int tid = threadIdx.x, wid = tid >> 5, lane = tid & 31;
    int bm = blockIdx.y * 128, bn = blockIdx.x * 256;
    int wm = wid & 1, wn = wid >> 1;          // warp tile: rows wm*64, cols wn*32

    float acc[4][4][4] = {};

    mg_issue(sbase, 0, 0, bm, bn, tid); CP_COMMIT();
    mg_issue(sbase, 1, 1, bm, bn, tid); CP_COMMIT();
    mg_issue(sbase, 2, 2, bm, bn, tid); CP_COMMIT();

    int l15 = lane & 15, l16 = lane >> 4;

    for (int i = 0; i < MG_ITERS; i++) {
        CP_WAIT2();
        __syncthreads();
        int s = i & 3;
        uint32_t ab = sbase + s * MG_STGSZ;
        uint32_t bb = ab + 2 * MG_ASZ;
        #pragma unroll
        for (int ks = 0; ks < 2; ks++) {
            int kc = ks * 2;
            uint32_t aoffw = (wm * 64 + l15) * MG_AROWB + (kc + l16) * 16;
            uint32_t baddr = bb + (wn * 32 + l15) * MG_AROWB + (kc + l16) * 16;
            uint32_t br[2][4];
            #pragma unroll
            for (int nb = 0; nb < 2; nb++)
                ldm4(br[nb][0], br[nb][1], br[nb][2], br[nb][3],
                     baddr + nb * 16 * MG_AROWB);
            // A hi pass
            {
                uint32_t ar[4][4];
                #pragma unroll
                for (int mi = 0; mi < 4; mi++)
                    ldm4(ar[mi][0], ar[mi][1], ar[mi][2], ar[mi][3],
                         ab + aoffw + mi * 16 * MG_AROWB);
                #pragma unroll
                for (int mi = 0; mi < 4; mi++) {
                    #pragma unroll
                    for (int nb = 0; nb < 2; nb++) {
                        mma16816(acc[mi][2 * nb + 0], ar[mi], br[nb][0], br[nb][2]);
                        mma16816(acc[mi][2 * nb + 1], ar[mi], br[nb][1], br[nb][3]);
                    }
                }
            }
            // A lo pass (same B fragments)
            {
                uint32_t ar[4][4];
                #pragma unroll
                for (int mi = 0; mi < 4; mi++)
                    ldm4(ar[mi][0], ar[mi][1], ar[mi][2], ar[mi][3],
                         ab + MG_ASZ + aoffw + mi * 16 * MG_AROWB);
                #pragma unroll
                for (int mi = 0; mi < 4; mi++) {
                    #pragma unroll
                    for (int nb = 0; nb < 2; nb++) {
                        mma16816(acc[mi][2 * nb + 0], ar[mi], br[nb][0], br[nb][2]);
                        mma16816(acc[mi][2 * nb + 1], ar[mi], br[nb][1], br[nb][3]);
                    }
                }
            }
        }
        if (i + 3 < MG_ITERS)
            mg_issue(sbase, (i + 3) & 3, i + 3, bm, bn, tid);
        CP_COMMIT();   // keep group counts uniform
    }

    // epilogue
    int lr = lane >> 2, lc = (lane & 3) * 2;
    #pragma unroll
    for (int mi = 0; mi < 4; mi++) {
        int row0 = bm + wm * 64 + mi * 16 + lr;
        int row1 = row0 + 8;
        float am0 = g_attn[row0], am1 = g_attn[row1];
        const float* vo0 = g_vo + (size_t)(row0 >> 6) * E_;
        const float* vo1 = g_vo + (size_t)(row1 >> 6) * E_;
        float* o0 = out + (size_t)row0 * E_;
        float* o1 = out + (size_t)row1 * E_;
        #pragma unroll
        for (int ni = 0; ni < 4; ni++) {
            int col = bn + wn * 32 + ni * 8 + lc;
            float2 r0, r1;
            r0.x = acc[mi][ni][0] + am0 * vo0[col]     + ob[col];
            r0.y = acc[mi][ni][1] + am0 * vo0[col + 1] + ob[col + 1];
            r1.x = acc[mi][ni][2] + am1 * vo1[col]     + ob[col];
            r1.y = acc[mi][ni][3] + am1 * vo1[col + 1] + ob[col + 1];
            *(float2*)(o0 + col) = r0;
            *(float2*)(o1 + col) = r1;
        }
    }
}

extern "C" void kernel_launch(void* const* d_in, const int* in_sizes, int n_in,
                              void* d_out, int out_size) {
    const float* re    = (const float*)d_in[0];
    const float* ctx   = (const float*)d_in[1];
    const float* qW    = (const float*)d_in[2];
    const float* qb    = (const float*)d_in[3];
    const float* kW    = (const float*)d_in[4];
    const float* kb    = (const float*)d_in[5];
    const float* vW    = (const float*)d_in[6];
    const float* vb    = (const float*)d_in[7];
    const float* oW    = (const float*)d_in[8];
    const float* ob    = (const float*)d_in[9];
    const float* lnq_g = (const float*)d_in[10];
    const float* lnq_b = (const float*)d_in[11];
    const float* lnk_g = (const float*)d_in[12];
    const float* lnk_b = (const float*)d_in[13];
    float* out = (float*)d_out;

    void *p_nk, *p_k, *p_v, *p_w, *p_gw, *p_vo, *p_qWT, *p_ahi, *p_alo, *p_bh;
    cudaGetSymbolAddress(&p_nk,  g_nk);
    cudaGetSymbolAddress(&p_k,   g_k);
    cudaGetSymbolAddress(&p_v,   g_v);
    cudaGetSymbolAddress(&p_w,   g_w);
    cudaGetSymbolAddress(&p_gw,  g_gw);
    cudaGetSymbolAddress(&p_vo,  g_vo);
    cudaGetSymbolAddress(&p_qWT, g_qWT);
    cudaGetSymbolAddress(&p_ahi, g_Ahi);
    cudaGetSymbolAddress(&p_alo, g_Alo);
    cudaGetSymbolAddress(&p_bh,  g_Bh);
    float* nk  = (float*)p_nk;
    float* k   = (float*)p_k;
    float* v   = (float*)p_v;
    float* w   = (float*)p_w;
    float* gw  = (float*)p_gw;
    float* vo  = (float*)p_vo;
    float* qWT = (float*)p_qWT;

    // 0. fp16 splits for the main GEMM operands
    splitA_kernel<<<(size_t)M_ * E_ / 4 / 256, 256>>>(re, (__half*)p_ahi, (__half*)p_alo);
    cvtB_kernel<<<(size_t)E_ * E_ / 4 / 256, 256>>>(oW, (__half*)p_bh);
    // 1. nk = LN(context)
    ln_ctx_kernel<<<B_, 256>>>(ctx, lnk_g, lnk_b);
    // 2. k = nk @ kW^T + kb ; v = nk @ vW^T + vb
    gemm64_nt<<<dim3(16, 16), 256>>>(nk, kW, kb, nullptr, k, nullptr, D_);
    gemm64_nt<<<dim3(16, 16), 256>>>(nk, vW, vb, nullptr, v, nullptr, D_);
    // 3. qWT = qW^T ; w = k @ qW ; gw = lnq_g * w
    transpose_kernel<<<dim3(32, 32), dim3(32, 8)>>>(qW, qWT);
    gemm64_nt<<<dim3(16, 16), 256>>>(k, qWT, nullptr, lnq_g, w, gw, E_);
    // 4. vo = v @ oW^T
    gemm64_nt<<<dim3(16, 16), 256>>>(v, oW, nullptr, nullptr, vo, nullptr, E_);
    // 5. per-batch scalars
    scalars_kernel<<<B_ / 8, 256>>>(qb, lnq_b);
    // 6. attn per (b,n) row
    attn_kernel<<<M_ / 8, 256>>>(re);
    // 7. out = re @ oW^T + attn*vo + ob  (mma.sync fp16 2-term)
    const int smem_bytes = MG_STAGES * MG_STGSZ;   // 163840
    cudaFuncSetAttribute(main_gemm_mma, cudaFuncAttributeMaxDynamicSharedMemorySize, smem_bytes);
    main_gemm_mma<<<dim3(4, 512), 512, smem_bytes>>>(ob, out);
}

// round 6
// speedup vs baseline: 5.2776x; 1.8241x over previous
#include <cuda_runtime.h>
#include <cuda_fp16.h>
#include <math.h>
#include <stdint.h>

#define B_ 1024
#define N_ 64
#define E_ 1024
#define D_ 512
#define M_ (B_*N_)   // 65536 rows

// -------- scratch (device globals; no allocation allowed) --------
__device__ __half g_nk_h [B_*D_];
__device__ __half g_kWh  [E_*D_];
__device__ __half g_vWh  [E_*D_];
__device__ __half g_qWTh [E_*E_];
__device__ float  g_k    [B_*E_];
__device__ __half g_k_h  [B_*E_];
__device__ __half g_v_h  [B_*E_];
__device__ float  g_w    [B_*E_];
__device__ float  g_gw   [B_*E_];
__device__ float  g_vo   [B_*E_];
__device__ float  g_Sg   [B_];
__device__ float  g_Sb   [B_];
__device__ float  g_attn [M_];
__device__ __half g_Ah   [(size_t)M_*E_];
__device__ __half g_Bh   [(size_t)E_*E_];

// ================= PTX helpers (compute_103-safe) ==========
__device__ __forceinline__ uint32_t smem_u32(const void* p) {
    uint32_t a;
    asm("{ .reg .u64 t; cvta.to.shared.u64 t, %1; cvt.u32.u64 %0, t; }" : "=r"(a) : "l"(p));
    return a;
}
__device__ __forceinline__ void cp16(uint32_t dst, const void* src) {
    asm volatile("cp.async.cg.shared.global [%0], [%1], 16;" :: "r"(dst), "l"(src));
}
#define CP_COMMIT() asm volatile("cp.async.commit_group;" ::: "memory")
#define CP_WAIT2()  asm volatile("cp.async.wait_group 2;" ::: "memory")
#define CP_WAIT1()  asm volatile("cp.async.wait_group 1;" ::: "memory")

__device__ __forceinline__ void ldm4(uint32_t& r0, uint32_t& r1, uint32_t& r2,
                                     uint32_t& r3, uint32_t a) {
    asm volatile("ldmatrix.sync.aligned.m8n8.x4.shared.b16 {%0,%1,%2,%3}, [%4];"
                 : "=r"(r0), "=r"(r1), "=r"(r2), "=r"(r3) : "r"(a));
}
__device__ __forceinline__ void mma16816(float* c, const uint32_t* a,
                                         uint32_t b0, uint32_t b1) {
    asm volatile("mma.sync.aligned.m16n8k16.row.col.f32.f16.f16.f32 "
                 "{%0,%1,%2,%3},{%4,%5,%6,%7},{%8,%9},{%0,%1,%2,%3};"
                 : "+f"(c[0]), "+f"(c[1]), "+f"(c[2]), "+f"(c[3])
                 : "r"(a[0]), "r"(a[1]), "r"(a[2]), "r"(a[3]), "r"(b0), "r"(b1));
}

// ================= converts =================
__global__ void cvt_kernel(const float* __restrict__ x, __half* __restrict__ h) {
    size_t i = ((size_t)blockIdx.x * blockDim.x + threadIdx.x) * 4;
    float4 v = *(const float4*)(x + i);
    __half2 a = __floats2half2_rn(v.x, v.y);
    __half2 b = __floats2half2_rn(v.z, v.w);
    uint2 p;
    p.x = *(uint32_t*)&a; p.y = *(uint32_t*)&b;
    *(uint2*)(h + i) = p;
}

// qW (ExE fp32) -> qWT fp16
__global__ void transpose_cvt_kernel(const float* __restrict__ in, __half* __restrict__ out) {
    __shared__ float t[32][33];
    int tx = threadIdx.x, ty = threadIdx.y;
    int bx = blockIdx.x * 32, by = blockIdx.y * 32;
    #pragma unroll
    for (int i = 0; i < 32; i += 8)
        t[ty + i][tx] = in[(size_t)(by + ty + i) * E_ + bx + tx];
    __syncthreads();
    #pragma unroll
    for (int i = 0; i < 32; i += 8)
        out[(size_t)(bx + ty + i) * E_ + by + tx] = __float2half(t[tx][ty + i]);
}

// -------- LayerNorm of context -> fp16 nk --------
__global__ void ln_ctx_kernel(const float* __restrict__ ctx,
                              const float* __restrict__ gam,
                              const float* __restrict__ bet) {
    int b = blockIdx.x, tid = threadIdx.x;
    const float* x = ctx + (size_t)b * D_;
    float v0 = x[tid], v1 = x[tid + 256];
    __shared__ float r1[256], r2[256];
    r1[tid] = v0 + v1;
    r2[tid] = v0 * v0 + v1 * v1;
    __syncthreads();
    for (int o = 128; o > 0; o >>= 1) {
        if (tid < o) { r1[tid] += r1[tid + o]; r2[tid] += r2[tid + o]; }
        __syncthreads();
    }
    float mu = r1[0] * (1.0f / D_);
    float var = r2[0] * (1.0f / D_) - mu * mu;
    float rstd = rsqrtf(var + 1e-5f);
    g_nk_h[(size_t)b * D_ + tid]       = __float2half((v0 - mu) * rstd * gam[tid]       + bet[tid]);
    g_nk_h[(size_t)b * D_ + tid + 256] = __float2half((v1 - mu) * rstd * gam[tid + 256] + bet[tid + 256]);
}

// ================= aux fp16 GEMM: C[1024x1024] = A(1024xK) @ B(1024xK)^T =================
// 128x128 tile, 256 threads, warp tile 64x32, BK=32, 3-stage cp.async.
#define AG_AROWB 80
#define AG_ASZ   (128*AG_AROWB)      // 10240
#define AG_STG   (2*AG_ASZ)          // 20480
#define AG_STAGES 3

__device__ __forceinline__ void ag_issue(uint32_t sbase, int stage, int it,
                                         int bm, int bn, int tid,
                                         const __half* A, const __half* Bm, int K) {
    int kk = it << 5;
    uint32_t ab = sbase + stage * AG_STG;
    uint32_t bb = ab + AG_ASZ;
    #pragma unroll
    for (int j = 0; j < 2; j++) {
        int id = tid + j * 256;
        int r = id >> 2, c = id & 3;
        cp16(ab + r * AG_AROWB + c * 16, A  + (size_t)(bm + r) * K + kk + c * 8);
        cp16(bb + r * AG_AROWB + c * 16, Bm + (size_t)(bn + r) * K + kk + c * 8);
    }
}

__global__ void __launch_bounds__(256, 1) gemm_h(
    const __half* __restrict__ A, const __half* __restrict__ Bm, int K,
    const float* __restrict__ bias, float* __restrict__ Cf, __half* __restrict__ Ch,
    const float* __restrict__ colmul, float* __restrict__ C2f) {
    extern __shared__ char smem[];
    uint32_t sbase = smem_u32(smem);
    int tid = threadIdx.x, wid = tid >> 5, lane = tid & 31;
    int bm = blockIdx.y * 128, bn = blockIdx.x * 128;
    int wm = wid & 1, wn = wid >> 1;
    int iters = K >> 5;

    float acc[4][4][4] = {};

    ag_issue(sbase, 0, 0, bm, bn, tid, A, Bm, K); CP_COMMIT();
    ag_issue(sbase, 1, 1, bm, bn, tid, A, Bm, K); CP_COMMIT();

    int l15 = lane & 15, l16 = lane >> 4;

    for (int i = 0; i < iters; i++) {
        CP_WAIT1();
        __syncthreads();
        int s = i % 3;
        uint32_t ab = sbase + s * AG_STG;
        uint32_t bb = ab + AG_ASZ;
        #pragma unroll
        for (int ks = 0; ks < 2; ks++) {
            int kc = ks * 2;
            uint32_t aaddr = ab + (wm * 64 + l15) * AG_AROWB + (kc + l16) * 16;
            uint32_t baddr = bb + (wn * 32 + l15) * AG_AROWB + (kc + l16) * 16;
            uint32_t ar[4][4], br[2][4];
            #pragma unroll
            for (int mi = 0; mi < 4; mi++)
                ldm4(ar[mi][0], ar[mi][1], ar[mi][2], ar[mi][3],
                     aaddr + mi * 16 * AG_AROWB);
            #pragma unroll
            for (int nb = 0; nb < 2; nb++)
                ldm4(br[nb][0], br[nb][1], br[nb][2], br[nb][3],
                     baddr + nb * 16 * AG_AROWB);
            #pragma unroll
            for (int mi = 0; mi < 4; mi++) {
                #pragma unroll
                for (int nb = 0; nb < 2; nb++) {
                    mma16816(acc[mi][2 * nb + 0], ar[mi], br[nb][0], br[nb][2]);
                    mma16816(acc[mi][2 * nb + 1], ar[mi], br[nb][1], br[nb][3]);
                }
            }
        }
        if (i + 2 < iters)
            ag_issue(sbase, (i + 2) % 3, i + 2, bm, bn, tid, A, Bm, K);
        CP_COMMIT();
    }

    int lr = lane >> 2, lc = (lane & 3) * 2;
    #pragma unroll
    for (int mi = 0; mi < 4; mi++) {
        int row0 = bm + wm * 64 + mi * 16 + lr;
        int row1 = row0 + 8;
        #pragma unroll
        for (int ni = 0; ni < 4; ni++) {
            int col = bn + wn * 32 + ni * 8 + lc;
            float b0 = bias ? bias[col] : 0.0f;
            float b1 = bias ? bias[col + 1] : 0.0f;
            float v00 = acc[mi][ni][0] + b0, v01 = acc[mi][ni][1] + b1;
            float v10 = acc[mi][ni][2] + b0, v11 = acc[mi][ni][3] + b1;
            if (Cf) {
                *(float2*)(Cf + (size_t)row0 * 1024 + col) = make_float2(v00, v01);
                *(float2*)(Cf + (size_t)row1 * 1024 + col) = make_float2(v10, v11);
            }
            if (Ch) {
                __half2 h0 = __floats2half2_rn(v00, v01);
                __half2 h1 = __floats2half2_rn(v10, v11);
                *(__half2*)(Ch + (size_t)row0 * 1024 + col) = h0;
                *(__half2*)(Ch + (size_t)row1 * 1024 + col) = h1;
            }
            if (C2f) {
                float c0 = colmul[col], c1 = colmul[col + 1];
                *(float2*)(C2f + (size_t)row0 * 1024 + col) = make_float2(c0 * v00, c1 * v01);
                *(float2*)(C2f + (size_t)row1 * 1024 + col) = make_float2(c0 * v10, c1 * v11);
            }
        }
    }
}

// ================= per-batch scalars / attn (fp32, unchanged) =================
__global__ void scalars_kernel(const float* __restrict__ qb,
                               const float* __restrict__ lnq_b) {
    int warp = threadIdx.x >> 5, lane = threadIdx.x & 31;
    int b = blockIdx.x * 8 + warp;
    const float* gw = g_gw + (size_t)b * E_;
    const float* w  = g_w  + (size_t)b * E_;
    const float* k  = g_k  + (size_t)b * E_;
    float sg = 0.f, sb = 0.f, cb = 0.f;
    for (int i = lane; i < E_; i += 32) {
        sg += gw[i];
        sb += lnq_b[i] * w[i];
        cb += qb[i] * k[i];
    }
    #pragma unroll
    for (int o = 16; o > 0; o >>= 1) {
        sg += __shfl_xor_sync(0xffffffffu, sg, o);
        sb += __shfl_xor_sync(0xffffffffu, sb, o);
        cb += __shfl_xor_sync(0xffffffffu, cb, o);
    }
    if (lane == 0) { g_Sg[b] = sg; g_Sb[b] = sb + cb; }
}

__global__ void attn_kernel(const float* __restrict__ re) {
    int warp = threadIdx.x >> 5, lane = threadIdx.x & 31;
    int m = blockIdx.x * 8 + warp;
    int b = m >> 6;
    const float* x  = re   + (size_t)m * E_;
    const float* wv = g_gw + (size_t)b * E_;
    float s1 = 0.f, s2 = 0.f, sd = 0.f;
    for (int i = lane; i < E_; i += 32) {
        float t = x[i];
        s1 += t;
        s2 += t * t;
        sd += t * wv[i];
    }
    #pragma unroll
    for (int o = 16; o > 0; o >>= 1) {
        s1 += __shfl_xor_sync(0xffffffffu, s1, o);
        s2 += __shfl_xor_sync(0xffffffffu, s2, o);
        sd += __shfl_xor_sync(0xffffffffu, sd, o);
    }
    if (lane == 0) {
        float mu = s1 * (1.0f / E_);
        float var = s2 * (1.0f / E_) - mu * mu;
        float rstd = rsqrtf(var + 1e-5f);
        float score = 0.03125f * (rstd * (sd - mu * g_Sg[b]) + g_Sb[b]);
        g_attn[m] = tanhf(score);
    }
}

// ================= main GEMM via mma.sync (single fp16 pass) =================
// out = re @ oW^T + attn*vo + ob;  CTA tile 128x256, 512 threads, warp 64x32,
// BK=32, 4-stage cp.async, 80B-padded smem rows.
#define MG_STAGES 4
#define MG_AROWB  80
#define MG_ASZ    (128*MG_AROWB)            // 10240
#define MG_BSZ    (256*MG_AROWB)            // 20480
#define MG_STGSZ  (MG_ASZ + MG_BSZ)         // 30720
#define MG_ITERS  32

__device__ __forceinline__ void mg_issue(uint32_t sbase, int stage, int it,
                                         int bm, int bn, int tid) {
    int kk = it << 5;
    uint32_t ab = sbase + stage * MG_STGSZ;
    uint32_t bb = ab + MG_ASZ;
    int ar = tid >> 2, ac = tid & 3;
    cp16(ab + ar * MG_AROWB + ac * 16,
         g_Ah + (size_t)(bm + ar) * E_ + kk + ac * 8);
    #pragma unroll
    for (int j = 0; j < 2; j++) {
        int id = tid + j * 512;
        int br = id >> 2, bc = id & 3;
        cp16(bb + br * MG_AROWB + bc * 16,
             g_Bh + (size_t)(bn + br) * E_ + kk + bc * 8);
    }
}

__global__ void __launch_bounds__(512, 1) main_gemm_mma(const float* __restrict__ ob,
                                                        float* __restrict__ out) {
    extern __shared__ char smem[];
    uint32_t sbase = smem_u32(smem);
    int tid = threadIdx.x, wid = tid >> 5, lane = tid & 31;
    int bm = blockIdx.y * 128, bn = blockIdx.x * 256;
    int wm = wid & 1, wn = wid >> 1;

    float acc[4][4][4] = {};

    mg_issue(sbase, 0, 0, bm, bn, tid); CP_COMMIT();
    mg_issue(sbase, 1, 1, bm, bn, tid); CP_COMMIT();
    mg_issue(sbase, 2, 2, bm, bn, tid); CP_COMMIT();

    int l15 = lane & 15, l16 = lane >> 4;

    for (int i = 0; i < MG_ITERS; i++) {
        CP_WAIT2();
        __syncthreads();
        int s = i & 3;
        uint32_t ab = sbase + s * MG_STGSZ;
        uint32_t bb = ab + MG_ASZ;
        #pragma unroll
        for (int ks = 0; ks < 2; ks++) {
            int kc = ks * 2;
            uint32_t aaddr = ab + (wm * 64 + l15) * MG_AROWB + (kc + l16) * 16;
            uint32_t baddr = bb + (wn * 32 + l15) * MG_AROWB + (kc + l16) * 16;
            uint32_t ar[4][4], br[2][4];
            #pragma unroll
            for (int mi = 0; mi < 4; mi++)
                ldm4(ar[mi][0], ar[mi][1], ar[mi][2], ar[mi][3],
                     aaddr + mi * 16 * MG_AROWB);
            #pragma unroll
            for (int nb = 0; nb < 2; nb++)
                ldm4(br[nb][0], br[nb][1], br[nb][2], br[nb][3],
                     baddr + nb * 16 * MG_AROWB);
            #pragma unroll
            for (int mi = 0; mi < 4; mi++) {
                #pragma unroll
                for (int nb = 0; nb < 2; nb++) {
                    mma16816(acc[mi][2 * nb + 0], ar[mi], br[nb][0], br[nb][2]);
                    mma16816(acc[mi][2 * nb + 1], ar[mi], br[nb][1], br[nb][3]);
                }
            }
        }
        if (i + 3 < MG_ITERS)
            mg_issue(sbase, (i + 3) & 3, i + 3, bm, bn, tid);
        CP_COMMIT();
    }

    int lr = lane >> 2, lc = (lane & 3) * 2;
    #pragma unroll
    for (int mi = 0; mi < 4; mi++) {
        int row0 = bm + wm * 64 + mi * 16 + lr;
        int row1 = row0 + 8;
        float am0 = g_attn[row0], am1 = g_attn[row1];
        const float* vo0 = g_vo + (size_t)(row0 >> 6) * E_;
        const float* vo1 = g_vo + (size_t)(row1 >> 6) * E_;
        float* o0 = out + (size_t)row0 * E_;
        float* o1 = out + (size_t)row1 * E_;
        #pragma unroll
        for (int ni = 0; ni < 4; ni++) {
            int col = bn + wn * 32 + ni * 8 + lc;
            float2 r0, r1;
            r0.x = acc[mi][ni][0] + am0 * vo0[col]     + ob[col];
            r0.y = acc[mi][ni][1] + am0 * vo0[col + 1] + ob[col + 1];
            r1.x = acc[mi][ni][2] + am1 * vo1[col]     + ob[col];
            r1.y = acc[mi][ni][3] + am1 * vo1[col + 1] + ob[col + 1];
            *(float2*)(o0 + col) = r0;
            *(float2*)(o1 + col) = r1;
        }
    }
}

extern "C" void kernel_launch(void* const* d_in, const int* in_sizes, int n_in,
                              void* d_out, int out_size) {
    const float* re    = (const float*)d_in[0];
    const float* ctx   = (const float*)d_in[1];
    const float* qW    = (const float*)d_in[2];
    const float* qb    = (const float*)d_in[3];
    const float* kW    = (const float*)d_in[4];
    const float* kb    = (const float*)d_in[5];
    const float* vW    = (const float*)d_in[6];
    const float* vb    = (const float*)d_in[7];
    const float* oW    = (const float*)d_in[8];
    const float* ob    = (const float*)d_in[9];
    const float* lnq_g = (const float*)d_in[10];
    const float* lnq_b = (const float*)d_in[11];
    const float* lnk_g = (const float*)d_in[12];
    const float* lnk_b = (const float*)d_in[13];
    float* out = (float*)d_out;

    void *p_nkh, *p_kwh, *p_vwh, *p_qwth, *p_k, *p_kh, *p_vh, *p_w, *p_gw, *p_vo, *p_ah, *p_bh;
    cudaGetSymbolAddress(&p_nkh,  g_nk_h);
    cudaGetSymbolAddress(&p_kwh,  g_kWh);
    cudaGetSymbolAddress(&p_vwh,  g_vWh);
    cudaGetSymbolAddress(&p_qwth, g_qWTh);
    cudaGetSymbolAddress(&p_k,    g_k);
    cudaGetSymbolAddress(&p_kh,   g_k_h);
    cudaGetSymbolAddress(&p_vh,   g_v_h);
    cudaGetSymbolAddress(&p_w,    g_w);
    cudaGetSymbolAddress(&p_gw,   g_gw);
    cudaGetSymbolAddress(&p_vo,   g_vo);
    cudaGetSymbolAddress(&p_ah,   g_Ah);
    cudaGetSymbolAddress(&p_bh,   g_Bh);

    const int ag_smem = AG_STAGES * AG_STG;     // 61440
    const int mg_smem = MG_STAGES * MG_STGSZ;   // 122880
    cudaFuncSetAttribute(gemm_h, cudaFuncAttributeMaxDynamicSharedMemorySize, ag_smem);
    cudaFuncSetAttribute(main_gemm_mma, cudaFuncAttributeMaxDynamicSharedMemorySize, mg_smem);

    // 0. fp16 conversions
    cvt_kernel<<<(size_t)M_ * E_ / 4 / 256, 256>>>(re, (__half*)p_ah);
    cvt_kernel<<<E_ * E_ / 4 / 256, 256>>>(oW, (__half*)p_bh);
    cvt_kernel<<<E_ * D_ / 4 / 256, 256>>>(kW, (__half*)p_kwh);
    cvt_kernel<<<E_ * D_ / 4 / 256, 256>>>(vW, (__half*)p_vwh);
    transpose_cvt_kernel<<<dim3(32, 32), dim3(32, 8)>>>(qW, (__half*)p_qwth);
    // 1. nk = LN(context) -> fp16
    ln_ctx_kernel<<<B_, 256>>>(ctx, lnk_g, lnk_b);
    // 2. k = nk @ kW^T + kb (fp32 + fp16);  v = nk @ vW^T + vb (fp16)
    gemm_h<<<dim3(8, 8), 256, ag_smem>>>((__half*)p_nkh, (__half*)p_kwh, D_,
        kb, (float*)p_k, (__half*)p_kh, nullptr, nullptr);
    gemm_h<<<dim3(8, 8), 256, ag_smem>>>((__half*)p_nkh, (__half*)p_vwh, D_,
        vb, nullptr, (__half*)p_vh, nullptr, nullptr);
    // 3. w = k @ qW (fp32) ; gw = lnq_g * w (fp32)
    gemm_h<<<dim3(8, 8), 256, ag_smem>>>((__half*)p_kh, (__half*)p_qwth, E_,
        nullptr, (float*)p_w, nullptr, lnq_g, (float*)p_gw);
    // 4. vo = v @ oW^T (fp32)
    gemm_h<<<dim3(8, 8), 256, ag_smem>>>((__half*)p_vh, (__half*)p_bh, E_,
        nullptr, (float*)p_vo, nullptr, nullptr, nullptr);
    // 5. per-batch scalars
    scalars_kernel<<<B_ / 8, 256>>>(qb, lnq_b);
    // 6. attn per (b,n) row
    attn_kernel<<<M_ / 8, 256>>>(re);
    // 7. out = re @ oW^T + attn*vo + ob  (single fp16 pass)
    main_gemm_mma<<<dim3(4, 512), 512, mg_smem>>>(ob, out);
}